// round 3
// baseline (speedup 1.0000x reference)
#include <cuda_runtime.h>
#include <cuda_bf16.h>

// Kanvolution2d: out[b,o,h,w] = sum_k w_out[o,k] * P_ok(x_k) / (1 + |Q_ok(x_k)|)
// B=4, C=16, H=W=32, O=32, K=144. Compute/issue-bound.
//
// R3: 512 small CTAs (8-row tiles, 64 thr) for occupancy/balance +
//     packed f32x2 FMA math (row pairs), weights duplicated in smem for
//     single-LDS.64 packed broadcast operands + float4 vectorized staging.

#define C_IN 16
#define O_OUT 32
#define HW 32
#define KTOT 144
#define TILE_ROWS 8
#define THREADS 64
#define XROWS (TILE_ROWS + 2)   // 10
#define XCOLS 40                // 4-col lead pad (aligned interior at [4..35]), halos at [3],[36]
#define XBASE 4

typedef unsigned long long ull;

__device__ __forceinline__ ull pk2(float a, float b) {
    ull r; asm("mov.b64 %0, {%1,%2};" : "=l"(r) : "f"(a), "f"(b)); return r;
}
__device__ __forceinline__ void upk2(ull v, float& a, float& b) {
    asm("mov.b64 {%0,%1}, %2;" : "=f"(a), "=f"(b) : "l"(v));
}
__device__ __forceinline__ ull ffma2(ull a, ull b, ull c) {
    ull d; asm("fma.rn.f32x2 %0, %1, %2, %3;" : "=l"(d) : "l"(a), "l"(b), "l"(c)); return d;
}
__device__ __forceinline__ ull fmul2(ull a, ull b) {
    ull d; asm("mul.rn.f32x2 %0, %1, %2;" : "=l"(d) : "l"(a), "l"(b)); return d;
}
__device__ __forceinline__ float frcp(float x) {
    float r; asm("rcp.approx.f32 %0, %1;" : "=f"(r) : "f"(x)); return r;
}

__global__ __launch_bounds__(THREADS)
void kanvolution_kernel(const float* __restrict__ x,
                        const float* __restrict__ w_p,
                        const float* __restrict__ w_q,
                        const float* __restrict__ w_out,
                        float* __restrict__ out) {
    const int tile = blockIdx.x;     // 0..3 (8-row slab)
    const int o    = blockIdx.y;     // 0..31
    const int b    = blockIdx.z;     // 0..3
    const int r0   = tile * TILE_ROWS;
    const int tid  = threadIdx.x;

    __shared__ float  s_x[C_IN][XROWS][XCOLS];
    __shared__ float2 s_wp[4][KTOT];   // w_out-folded P coeffs, duplicated (packed)
    __shared__ float2 s_wq[2][KTOT];   // Q coeffs, duplicated (packed)

    // --- stage weights (fold w_out into P; duplicate for f32x2 broadcast) ---
    for (int k = tid; k < KTOT; k += THREADS) {
        float wo = w_out[o * KTOT + k];
        #pragma unroll
        for (int p = 0; p < 4; p++) {
            float v = wo * w_p[(o * 4 + p) * KTOT + k];
            s_wp[p][k] = make_float2(v, v);
        }
        #pragma unroll
        for (int q = 0; q < 2; q++) {
            float v = w_q[(o * 2 + q) * KTOT + k];
            s_wq[q][k] = make_float2(v, v);
        }
    }

    // --- zero halo columns ([3] and [36]) ---
    for (int idx = tid; idx < C_IN * XROWS; idx += THREADS) {
        int c = idx / XROWS, rr = idx % XROWS;
        s_x[c][rr][XBASE - 1]  = 0.0f;
        s_x[c][rr][XBASE + 32] = 0.0f;
    }

    // --- stage x slab, vectorized: 1280 float4 / 64 thr = 20 iters ---
    // interior columns [4..35] are 16B-aligned (base offset = (c*10+rr)*160+16)
    for (int idx = tid; idx < C_IN * XROWS * (HW / 4); idx += THREADS) {
        int f4 = idx & 7;          // which float4 within the 32-col row
        int t  = idx >> 3;
        int rr = t % XROWS;
        int c  = t / XROWS;
        int h  = r0 - 1 + rr;
        float4 v = make_float4(0.f, 0.f, 0.f, 0.f);
        if (h >= 0 && h < HW)
            v = *(const float4*)&x[((b * C_IN + c) * HW + h) * HW + f4 * 4];
        *(float4*)&s_x[c][rr][XBASE + f4 * 4] = v;
    }
    __syncthreads();

    const int ow    = tid & 31;        // output column
    const int rbase = (tid >> 5) * 4;  // warp 0 -> rows 0..3, warp 1 -> rows 4..7

    ull accA = 0ULL;  // packed (row0, row1) accumulators — bits 0 == (0.f, 0.f)
    ull accB = 0ULL;  // packed (row2, row3)

    for (int c = 0; c < C_IN; c++) {
        #pragma unroll
        for (int j = 0; j < 3; j++) {
            float xv[6];
            #pragma unroll
            for (int rr = 0; rr < 6; rr++)
                xv[rr] = s_x[c][rbase + rr][XBASE - 1 + ow + j];

            // packed x pairs per kernel-row offset i:
            //   i: pairA = (xv[i], xv[i+1])  -> rows (0,1)
            //      pairB = (xv[i+2], xv[i+3])-> rows (2,3)
            ull p01 = pk2(xv[0], xv[1]);
            ull p12 = pk2(xv[1], xv[2]);
            ull p23 = pk2(xv[2], xv[3]);
            ull p34 = pk2(xv[3], xv[4]);
            ull p45 = pk2(xv[4], xv[5]);
            ull xa[3] = {p01, p12, p23};
            ull xb[3] = {p23, p34, p45};

            #pragma unroll
            for (int i = 0; i < 3; i++) {
                const int k = c * 9 + i * 3 + j;
                const ull w0 = *(const ull*)&s_wp[0][k];
                const ull w1 = *(const ull*)&s_wp[1][k];
                const ull w2 = *(const ull*)&s_wp[2][k];
                const ull w3 = *(const ull*)&s_wp[3][k];
                const ull q1 = *(const ull*)&s_wq[0][k];
                const ull q2 = *(const ull*)&s_wq[1][k];

                {   // pair A: output rows (rbase+0, rbase+1)
                    const ull X = xa[i];
                    ull sp = ffma2(ffma2(ffma2(w3, X, w2), X, w1), X, w0);
                    ull sq = fmul2(ffma2(q2, X, q1), X);
                    float s0, s1; upk2(sq, s0, s1);
                    float r0_ = frcp(1.0f + fabsf(s0));
                    float r1_ = frcp(1.0f + fabsf(s1));
                    accA = ffma2(sp, pk2(r0_, r1_), accA);
                }
                {   // pair B: output rows (rbase+2, rbase+3)
                    const ull X = xb[i];
                    ull sp = ffma2(ffma2(ffma2(w3, X, w2), X, w1), X, w0);
                    ull sq = fmul2(ffma2(q2, X, q1), X);
                    float s0, s1; upk2(sq, s0, s1);
                    float r0_ = frcp(1.0f + fabsf(s0));
                    float r1_ = frcp(1.0f + fabsf(s1));
                    accB = ffma2(sp, pk2(r0_, r1_), accB);
                }
            }
        }
    }

    float a0, a1, a2, a3;
    upk2(accA, a0, a1);
    upk2(accB, a2, a3);
    float res[4] = {a0, a1, a2, a3};
    #pragma unroll
    for (int r = 0; r < 4; r++) {
        const int oh = r0 + rbase + r;
        out[((b * O_OUT + o) * HW + oh) * HW + ow] = res[r];
    }
}

extern "C" void kernel_launch(void* const* d_in, const int* in_sizes, int n_in,
                              void* d_out, int out_size) {
    const float* x     = (const float*)d_in[0];  // [4,16,32,32]
    const float* w_p   = (const float*)d_in[1];  // [32,4,16,3,3]
    const float* w_q   = (const float*)d_in[2];  // [32,2,16,3,3]
    const float* w_out = (const float*)d_in[3];  // [32,16,3,3]
    float* out = (float*)d_out;                  // [4,32,32,32]

    dim3 grid(HW / TILE_ROWS, O_OUT, 4);  // (4, 32, 4) = 512 CTAs x 64 threads
    kanvolution_kernel<<<grid, THREADS>>>(x, w_p, w_q, w_out, out);
}

// round 7
// speedup vs baseline: 1.2448x; 1.2448x over previous
#include <cuda_runtime.h>
#include <cuda_bf16.h>

// Kanvolution2d: out[b,o,h,w] = sum_k w_out[o,k] * P_ok(x_k) / (1 + |Q_ok(x_k)|)
// B=4, C=16, H=W=32, O=32, K=144.
//
// R7 (= R4/R6 resubmit, broker timeouts): latency-bound fix — 4x more warps.
// 512 CTAs x 256 threads; the C=16 channel sum is split across 4 warp-groups
// (4 channels each, scalar math, 4 rows/thread), combined via a smem
// reduction. ~4096 warps total (~6.9/scheduler) vs 1024 at R3.

#define C_IN 16
#define O_OUT 32
#define HW 32
#define KTOT 144
#define TILE_ROWS 8
#define THREADS 256
#define XROWS (TILE_ROWS + 2)   // 10
#define XCOLS 40                // interior 16B-aligned at [4..35], halos [3],[36]
#define XBASE 4

__device__ __forceinline__ float frcp(float x) {
    float r; asm("rcp.approx.f32 %0, %1;" : "=f"(r) : "f"(x)); return r;
}

__global__ __launch_bounds__(THREADS)
void kanvolution_kernel(const float* __restrict__ x,
                        const float* __restrict__ w_p,
                        const float* __restrict__ w_q,
                        const float* __restrict__ w_out,
                        float* __restrict__ out) {
    const int tile = blockIdx.x;     // 0..3 (8-row slab)
    const int o    = blockIdx.y;     // 0..31
    const int b    = blockIdx.z;     // 0..3
    const int r0   = tile * TILE_ROWS;
    const int tid  = threadIdx.x;

    __shared__ float s_x[C_IN][XROWS][XCOLS];   // 25.6 KB
    __shared__ float s_wp[4][KTOT];             // w_out-folded P coeffs
    __shared__ float s_wq[2][KTOT];
    __shared__ float4 s_red[4][64];             // per-group partials (4 rows packed)

    // --- stage weights (fold w_out into P) ---
    for (int k = tid; k < KTOT; k += THREADS) {
        float wo = w_out[o * KTOT + k];
        #pragma unroll
        for (int p = 0; p < 4; p++)
            s_wp[p][k] = wo * w_p[(o * 4 + p) * KTOT + k];
        s_wq[0][k] = w_q[(o * 2 + 0) * KTOT + k];
        s_wq[1][k] = w_q[(o * 2 + 1) * KTOT + k];
    }

    // --- zero halo columns ---
    for (int idx = tid; idx < C_IN * XROWS; idx += THREADS) {
        int c = idx / XROWS, rr = idx % XROWS;
        s_x[c][rr][XBASE - 1]  = 0.0f;
        s_x[c][rr][XBASE + 32] = 0.0f;
    }

    // --- stage x slab, float4 vectorized: 1280 ld/st over 256 thr = 5 iters ---
    const float* xb = x + b * (C_IN * HW * HW);
    for (int idx = tid; idx < C_IN * XROWS * (HW / 4); idx += THREADS) {
        int f4 = idx & 7;
        int t  = idx >> 3;
        int rr = t % XROWS;
        int c  = t / XROWS;
        int h  = r0 - 1 + rr;
        float4 v = make_float4(0.f, 0.f, 0.f, 0.f);
        if (h >= 0 && h < HW)
            v = *(const float4*)&xb[(c * HW + h) * HW + f4 * 4];
        *(float4*)&s_x[c][rr][XBASE + f4 * 4] = v;
    }
    __syncthreads();

    const int g     = tid >> 6;          // channel group 0..3 (channels 4g..4g+3)
    const int t64   = tid & 63;
    const int ow    = t64 & 31;          // output column
    const int rbase = (t64 >> 5) * 4;    // rows rbase..rbase+3 within slab

    float acc[4] = {0.f, 0.f, 0.f, 0.f};

    const int cbeg = g * 4;
    #pragma unroll
    for (int cc = 0; cc < 4; cc++) {
        const int c = cbeg + cc;
        #pragma unroll
        for (int j = 0; j < 3; j++) {
            float xv[6];
            #pragma unroll
            for (int rr = 0; rr < 6; rr++)
                xv[rr] = s_x[c][rbase + rr][XBASE - 1 + ow + j];

            #pragma unroll
            for (int i = 0; i < 3; i++) {
                const int k = c * 9 + i * 3 + j;
                const float w0 = s_wp[0][k];
                const float w1 = s_wp[1][k];
                const float w2 = s_wp[2][k];
                const float w3 = s_wp[3][k];
                const float q1 = s_wq[0][k];
                const float q2 = s_wq[1][k];
                #pragma unroll
                for (int r = 0; r < 4; r++) {
                    const float xx = xv[r + i];
                    float sp = fmaf(fmaf(fmaf(w3, xx, w2), xx, w1), xx, w0);
                    float sq = fmaf(q2, xx, q1) * xx;
                    float rc = frcp(1.0f + fabsf(sq));
                    acc[r] = fmaf(sp, rc, acc[r]);
                }
            }
        }
    }

    // --- cross-group reduction (4 partials per output pixel) ---
    s_red[g][t64] = make_float4(acc[0], acc[1], acc[2], acc[3]);
    __syncthreads();

    if (tid < 64) {
        float4 a  = s_red[0][t64];
        float4 b1 = s_red[1][t64];
        float4 c1 = s_red[2][t64];
        float4 d1 = s_red[3][t64];
        float res[4] = {a.x + b1.x + c1.x + d1.x,
                        a.y + b1.y + c1.y + d1.y,
                        a.z + b1.z + c1.z + d1.z,
                        a.w + b1.w + c1.w + d1.w};
        #pragma unroll
        for (int r = 0; r < 4; r++) {
            const int oh = r0 + rbase + r;
            out[((b * O_OUT + o) * HW + oh) * HW + ow] = res[r];
        }
    }
}

extern "C" void kernel_launch(void* const* d_in, const int* in_sizes, int n_in,
                              void* d_out, int out_size) {
    const float* x     = (const float*)d_in[0];  // [4,16,32,32]
    const float* w_p   = (const float*)d_in[1];  // [32,4,16,3,3]
    const float* w_q   = (const float*)d_in[2];  // [32,2,16,3,3]
    const float* w_out = (const float*)d_in[3];  // [32,16,3,3]
    float* out = (float*)d_out;                  // [4,32,32,32]

    dim3 grid(HW / TILE_ROWS, O_OUT, 4);  // (4, 32, 4) = 512 CTAs x 256 threads
    kanvolution_kernel<<<grid, THREADS>>>(x, w_p, w_q, w_out, out);
}